// round 1
// baseline (speedup 1.0000x reference)
#include <cuda_runtime.h>
#include <cstdint>

// ---------------------------------------------------------------------------
// Problem constants (B=8192, N_IN=1024, N=2048)
// ---------------------------------------------------------------------------
#define FN   2048          // complex signal length N
#define FT   256           // threads per fused CTA
#define GEMM_N 4096        // 2*N
#define GEMM_K 1024        // N_IN

// Scratch for inputs @ w_ih.T  : (B, 2N) fp32 = 128MB (static device, no alloc)
__device__ float g_mul[8192ULL * 4096ULL];

// ---------------------------------------------------------------------------
// Kernel 1: C[m,j] = sum_k A[m,k] * B[j,k]   (NT GEMM, fp32)
// BM=BN=128, BK=16, 256 threads, 8x8 per thread
// ---------------------------------------------------------------------------
__global__ __launch_bounds__(256) void gemm_nt_kernel(
    const float* __restrict__ A,   // (M, K)
    const float* __restrict__ B,   // (N, K)
    float* __restrict__ C,         // (M, N)
    int M, int N, int K)
{
    constexpr int BM = 128, BN = 128, BK = 16, TM = 8, TN = 8;
    __shared__ float As[BK][BM + 8];
    __shared__ float Bs[BK][BN + 8];

    const int tid = threadIdx.x;
    const int tx = tid & 15;        // 0..15  -> column group
    const int ty = tid >> 4;        // 0..15  -> row group
    const int bm = blockIdx.y * BM;
    const int bn = blockIdx.x * BN;

    const int ldr = tid >> 2;        // 0..63 (row within half-tile)
    const int ldc = (tid & 3) * 4;   // k-offset (float4)

    float acc[TM][TN];
    #pragma unroll
    for (int i = 0; i < TM; ++i)
        #pragma unroll
        for (int j = 0; j < TN; ++j) acc[i][j] = 0.0f;

    for (int k0 = 0; k0 < K; k0 += BK) {
        #pragma unroll
        for (int h = 0; h < 2; ++h) {
            int row = ldr + h * 64;
            float4 a = *(const float4*)(A + (size_t)(bm + row) * K + k0 + ldc);
            As[ldc + 0][row] = a.x; As[ldc + 1][row] = a.y;
            As[ldc + 2][row] = a.z; As[ldc + 3][row] = a.w;
            float4 b = *(const float4*)(B + (size_t)(bn + row) * K + k0 + ldc);
            Bs[ldc + 0][row] = b.x; Bs[ldc + 1][row] = b.y;
            Bs[ldc + 2][row] = b.z; Bs[ldc + 3][row] = b.w;
        }
        __syncthreads();

        #pragma unroll
        for (int k = 0; k < BK; ++k) {
            float4 a0 = *(const float4*)&As[k][ty * TM];
            float4 a1 = *(const float4*)&As[k][ty * TM + 4];
            float4 b0 = *(const float4*)&Bs[k][tx * TN];
            float4 b1 = *(const float4*)&Bs[k][tx * TN + 4];
            float rm[TM] = {a0.x, a0.y, a0.z, a0.w, a1.x, a1.y, a1.z, a1.w};
            float rn[TN] = {b0.x, b0.y, b0.z, b0.w, b1.x, b1.y, b1.z, b1.w};
            #pragma unroll
            for (int i = 0; i < TM; ++i)
                #pragma unroll
                for (int j = 0; j < TN; ++j)
                    acc[i][j] = fmaf(rm[i], rn[j], acc[i][j]);
        }
        __syncthreads();
    }

    #pragma unroll
    for (int i = 0; i < TM; ++i) {
        float* crow = C + (size_t)(bm + ty * TM + i) * N + bn + tx * TN;
        *(float4*)(crow)     = make_float4(acc[i][0], acc[i][1], acc[i][2], acc[i][3]);
        *(float4*)(crow + 4) = make_float4(acc[i][4], acc[i][5], acc[i][6], acc[i][7]);
    }
}

// ---------------------------------------------------------------------------
// Householder reflection helper: z -= (2/|v|^2) * <z, conj(v)> * v  (in smem)
// ---------------------------------------------------------------------------
__device__ __forceinline__ void block_reflect(
    float2* z, const float* __restrict__ vre, const float* __restrict__ vim,
    float (*red)[8], int tid)
{
    float sr = 0.f, si = 0.f, sq = 0.f;
    for (int i = tid; i < FN; i += FT) {
        float zr = z[i].x, zi = z[i].y;
        float vr = vre[i], vi = vim[i];
        sr += zr * vr + zi * vi;        // Re(z * conj(v))
        si += zi * vr - zr * vi;        // Im(z * conj(v))
        sq += vr * vr + vi * vi;
    }
    #pragma unroll
    for (int o = 16; o; o >>= 1) {
        sr += __shfl_xor_sync(0xffffffffu, sr, o);
        si += __shfl_xor_sync(0xffffffffu, si, o);
        sq += __shfl_xor_sync(0xffffffffu, sq, o);
    }
    int w = tid >> 5;
    if ((tid & 31) == 0) { red[0][w] = sr; red[1][w] = si; red[2][w] = sq; }
    __syncthreads();
    sr = si = sq = 0.f;
    #pragma unroll
    for (int i = 0; i < 8; ++i) { sr += red[0][i]; si += red[1][i]; sq += red[2][i]; }
    float f  = 2.0f / sq;
    float fr = f * sr, fi = f * si;
    for (int i = tid; i < FN; i += FT) {
        float vr = vre[i], vi = vim[i];
        float zr = z[i].x, zi = z[i].y;
        z[i] = make_float2(zr - (fr * vr - fi * vi),
                           zi - (fr * vi + fi * vr));
    }
    __syncthreads();
}

// ---------------------------------------------------------------------------
// Kernel 2: fused URNN pipeline. 1 CTA = 1 batch row. Stockham radix-2 FFT.
// ---------------------------------------------------------------------------
__global__ __launch_bounds__(FT) void urnn_fused_kernel(
    const float* __restrict__ state,   // (B, 2N)
    const float* __restrict__ gin,     // (B, 2N) = inputs @ w_ih.T
    const float* __restrict__ b_h,
    const float* __restrict__ d1w, const float* __restrict__ r1re, const float* __restrict__ r1im,
    const float* __restrict__ d2w, const float* __restrict__ r2re, const float* __restrict__ r2im,
    const float* __restrict__ d3w, const int* __restrict__ perm,
    float* __restrict__ out)           // (B, 2N)
{
    __shared__ float2 bA[FN];
    __shared__ float2 bB[FN];
    __shared__ float2 tw[FN / 2];      // tw[k] = exp(-2*pi*i*k/FN)
    __shared__ float  red[3][8];

    const int tid = threadIdx.x;
    const size_t b = blockIdx.x;
    const float* srow = state + b * (2 * FN);
    const float* grow = gin   + b * (2 * FN);
    float*       orow = out   + b * (2 * FN);

    // twiddle table (per CTA, cheap: 4 sincos/thread)
    for (int i = tid; i < FN / 2; i += FT) {
        float s, c;
        __sincosf(-6.283185307179586f * (float)i / (float)FN, &s, &c);
        tw[i] = make_float2(c, s);
    }

    // load state + diag1: z = exp(i*d1)*state_c
    for (int i = tid; i < FN; i += FT) {
        float re = srow[i], im = srow[FN + i];
        float s, c; __sincosf(d1w[i], &s, &c);
        bA[i] = make_float2(c * re - s * im, s * re + c * im);
    }
    __syncthreads();

    float2 *x = bA, *y = bB;

    // ---- forward FFT (Stockham DIF, natural order in/out), 11 stages ----
    for (int m = 1; m < FN; m <<= 1) {
        for (int t = tid; t < FN / 2; t += FT) {
            int jm = t & ~(m - 1);
            float2 c0 = x[t], c1 = x[t + FN / 2];
            float2 w  = tw[jm];
            float dr = c0.x - c1.x, di = c0.y - c1.y;
            y[t + jm]     = make_float2(c0.x + c1.x, c0.y + c1.y);
            y[t + jm + m] = make_float2(w.x * dr - w.y * di,
                                        w.x * di + w.y * dr);
        }
        __syncthreads();
        float2* tmp = x; x = y; y = tmp;
    }

    // ---- reflect 1 ----
    block_reflect(x, r1re, r1im, red, tid);

    // ---- permutation + diag2 (gather x -> y) ----
    for (int i = tid; i < FN; i += FT) {
        float2 zp = x[perm[i]];
        float s, c; __sincosf(d2w[i], &s, &c);
        y[i] = make_float2(c * zp.x - s * zp.y, s * zp.x + c * zp.y);
    }
    __syncthreads();
    { float2* tmp = x; x = y; y = tmp; }

    // ---- inverse FFT (conjugate twiddles; 1/N folded into final stage) ----
    for (int m = 1; m < FN; m <<= 1) {
        for (int t = tid; t < FN / 2; t += FT) {
            int jm = t & ~(m - 1);
            float2 c0 = x[t], c1 = x[t + FN / 2];
            float2 w  = tw[jm];              // use conj(w)
            float dr = c0.x - c1.x, di = c0.y - c1.y;
            y[t + jm]     = make_float2(c0.x + c1.x, c0.y + c1.y);
            y[t + jm + m] = make_float2(w.x * dr + w.y * di,
                                        w.x * di - w.y * dr);
        }
        __syncthreads();
        float2* tmp = x; x = y; y = tmp;
    }

    // ---- reflect 2 (linear, so 1/N scale commutes; applied at the end) ----
    block_reflect(x, r2re, r2im, red, tid);

    // ---- diag3 * (1/N) + add inputs_c + modReLU + store ----
    const float invN = 1.0f / (float)FN;
    for (int i = tid; i < FN; i += FT) {
        float2 zc = x[i];
        float s, c; __sincosf(d3w[i], &s, &c);
        float zr = (c * zc.x - s * zc.y) * invN;
        float zi = (s * zc.x + c * zc.y) * invN;
        float pr = grow[i]      + zr;
        float pi = grow[FN + i] + zi;
        float norm = sqrtf(pr * pr + pi * pi);
        float sc = fmaxf(norm + b_h[i], 0.0f) / (norm + 1e-6f);
        orow[i]      = pr * sc;
        orow[FN + i] = pi * sc;
    }
}

// ---------------------------------------------------------------------------
// Launch
// ---------------------------------------------------------------------------
extern "C" void kernel_launch(void* const* d_in, const int* in_sizes, int n_in,
                              void* d_out, int out_size)
{
    const float* inputs = (const float*)d_in[0];
    const float* state  = (const float*)d_in[1];
    const float* w_ih   = (const float*)d_in[2];
    const float* b_h    = (const float*)d_in[3];
    const float* d1w    = (const float*)d_in[4];
    const float* r1re   = (const float*)d_in[5];
    const float* r1im   = (const float*)d_in[6];
    const float* d2w    = (const float*)d_in[7];
    const float* r2re   = (const float*)d_in[8];
    const float* r2im   = (const float*)d_in[9];
    const float* d3w    = (const float*)d_in[10];
    const int*   perm   = (const int*)d_in[11];
    float* out = (float*)d_out;

    const int B = in_sizes[1] / (2 * FN);   // 8192

    float* gmul = nullptr;
    cudaGetSymbolAddress((void**)&gmul, g_mul);

    // GEMM: (B x 1024) @ (4096 x 1024)^T -> (B x 4096)
    dim3 ggrid(GEMM_N / 128, B / 128);
    gemm_nt_kernel<<<ggrid, 256>>>(inputs, w_ih, gmul, B, GEMM_N, GEMM_K);

    // Fused URNN pipeline: one CTA per batch row
    urnn_fused_kernel<<<B, FT>>>(state, gmul, b_h,
                                 d1w, r1re, r1im,
                                 d2w, r2re, r2im,
                                 d3w, perm, out);
}

// round 2
// speedup vs baseline: 1.7719x; 1.7719x over previous
#include <cuda_runtime.h>
#include <cuda_bf16.h>
#include <cstdint>

// ---------------------------------------------------------------------------
// Problem constants (B=8192, N_IN=1024, N=2048)
// ---------------------------------------------------------------------------
#define FN   2048
#define FT   512
#define GM   8192
#define GN   4096
#define GK   1024

// Static scratch (no allocs allowed)
__device__ float         g_mul[8192ULL * 4096ULL];   // GEMM output (B, 2N)
__device__ __nv_bfloat16 g_Ah[8192ULL * 1024ULL];
__device__ __nv_bfloat16 g_Al[8192ULL * 1024ULL];
__device__ __nv_bfloat16 g_Bh[4096ULL * 1024ULL];
__device__ __nv_bfloat16 g_Bl[4096ULL * 1024ULL];

// ---------------------------------------------------------------------------
// Split fp32 -> bf16 hi + bf16 lo  (a = hi + lo + O(2^-18 |a|))
// ---------------------------------------------------------------------------
__global__ void split_kernel(const float* __restrict__ src,
                             __nv_bfloat16* __restrict__ hi,
                             __nv_bfloat16* __restrict__ lo, int n)
{
    int i = blockIdx.x * blockDim.x + threadIdx.x;
    if (i < n) {
        float v = src[i];
        __nv_bfloat16 h = __float2bfloat16(v);
        hi[i] = h;
        lo[i] = __float2bfloat16(v - __bfloat162float(h));
    }
}

// ---------------------------------------------------------------------------
// bf16 split GEMM:  C[m,n] = sum_k A[m,k]*B[n,k]  (fp32 via 3 bf16 passes)
// 128x128x32 tiles, 256 thr (8 warps 4x2), mma.sync m16n8k16, cp.async 2-stage
// ---------------------------------------------------------------------------
__device__ __forceinline__ void cp_async16(void* smem, const void* gmem)
{
    uint32_t s = (uint32_t)__cvta_generic_to_shared(smem);
    asm volatile("cp.async.cg.shared.global [%0], [%1], 16;\n" :: "r"(s), "l"(gmem));
}

__device__ __forceinline__ void ldsm_x4(uint32_t* r, const void* p)
{
    uint32_t s = (uint32_t)__cvta_generic_to_shared(p);
    asm volatile("ldmatrix.sync.aligned.m8n8.x4.shared.b16 {%0,%1,%2,%3}, [%4];\n"
                 : "=r"(r[0]), "=r"(r[1]), "=r"(r[2]), "=r"(r[3]) : "r"(s));
}

__device__ __forceinline__ void mma16816(float* c, const uint32_t* a, const uint32_t* b)
{
    asm volatile(
        "mma.sync.aligned.m16n8k16.row.col.f32.bf16.bf16.f32 "
        "{%0,%1,%2,%3}, {%4,%5,%6,%7}, {%8,%9}, {%0,%1,%2,%3};\n"
        : "+f"(c[0]), "+f"(c[1]), "+f"(c[2]), "+f"(c[3])
        : "r"(a[0]), "r"(a[1]), "r"(a[2]), "r"(a[3]), "r"(b[0]), "r"(b[1]));
}

#define SROW 40   // smem row stride in halves (80B: conflict-free for ldmatrix)

__global__ __launch_bounds__(256) void gemm_bf16_split(
    const __nv_bfloat16* __restrict__ Ah, const __nv_bfloat16* __restrict__ Al,
    const __nv_bfloat16* __restrict__ Bh, const __nv_bfloat16* __restrict__ Bl,
    float* __restrict__ C)
{
    __shared__ __nv_bfloat16 As[2][128 * SROW];
    __shared__ __nv_bfloat16 Bs[2][128 * SROW];

    const int tid  = threadIdx.x;
    const int wid  = tid >> 5, lane = tid & 31;
    const int wm   = wid >> 1, wn = wid & 1;     // warp grid 4(M) x 2(N)
    const int bm   = blockIdx.y * 128, bn = blockIdx.x * 128;

    const int NIT = 3 * (GK / 32);               // 96 tile iterations

    float acc[2][8][4];
    #pragma unroll
    for (int mi = 0; mi < 2; ++mi)
        #pragma unroll
        for (int ni = 0; ni < 8; ++ni)
            #pragma unroll
            for (int j = 0; j < 4; ++j) acc[mi][ni][j] = 0.0f;

    auto load_tiles = [&](int st, int it) {
        int pass = it >> 5;
        const __nv_bfloat16* Ap = (pass == 1) ? Al : Ah;
        const __nv_bfloat16* Bp = (pass == 2) ? Bl : Bh;
        int kk = (it & 31) * 32;
        #pragma unroll
        for (int j = 0; j < 2; ++j) {
            int c   = tid + j * 256;             // 512 16B-chunks per operand
            int row = c >> 2;
            int off = (c & 3) * 8;               // halves
            cp_async16(&As[st][row * SROW + off],
                       Ap + (size_t)(bm + row) * GK + kk + off);
            cp_async16(&Bs[st][row * SROW + off],
                       Bp + (size_t)(bn + row) * GK + kk + off);
        }
        asm volatile("cp.async.commit_group;\n");
    };

    load_tiles(0, 0);

    for (int it = 0; it < NIT; ++it) {
        int st = it & 1;
        if (it + 1 < NIT) {
            load_tiles(st ^ 1, it + 1);
            asm volatile("cp.async.wait_group 1;\n");
        } else {
            asm volatile("cp.async.wait_group 0;\n");
        }
        __syncthreads();

        #pragma unroll
        for (int ks = 0; ks < 2; ++ks) {
            uint32_t a[2][4], b[8][2];
            // A fragments: rows wm*32 + mi*16, ldmatrix x4
            int ra = wm * 32 + (lane & 7) + ((lane & 8) ? 8 : 0);
            int ca = ks * 16 + ((lane & 16) ? 8 : 0);
            #pragma unroll
            for (int mi = 0; mi < 2; ++mi)
                ldsm_x4(a[mi], &As[st][(ra + mi * 16) * SROW + ca]);
            // B fragments: 4 x ldmatrix x4, each covers 2 n-tiles
            int rb = wn * 64 + (lane & 7) + ((lane & 16) ? 8 : 0);
            int cb = ks * 16 + ((lane & 8) ? 8 : 0);
            #pragma unroll
            for (int g = 0; g < 4; ++g) {
                uint32_t r[4];
                ldsm_x4(r, &Bs[st][(rb + g * 16) * SROW + cb]);
                b[2 * g][0] = r[0]; b[2 * g][1] = r[1];
                b[2 * g + 1][0] = r[2]; b[2 * g + 1][1] = r[3];
            }
            #pragma unroll
            for (int mi = 0; mi < 2; ++mi)
                #pragma unroll
                for (int ni = 0; ni < 8; ++ni)
                    mma16816(acc[mi][ni], a[mi], b[ni]);
        }
        __syncthreads();
    }

    // epilogue: direct stores (c0,c1)->(r, c..c+1), (c2,c3)->(r+8, ...)
    #pragma unroll
    for (int mi = 0; mi < 2; ++mi) {
        #pragma unroll
        for (int ni = 0; ni < 8; ++ni) {
            int row = bm + wm * 32 + mi * 16 + (lane >> 2);
            int col = bn + wn * 64 + ni * 8 + (lane & 3) * 2;
            float2* p0 = (float2*)(C + (size_t)row * GN + col);
            float2* p1 = (float2*)(C + (size_t)(row + 8) * GN + col);
            *p0 = make_float2(acc[mi][ni][0], acc[mi][ni][1]);
            *p1 = make_float2(acc[mi][ni][2], acc[mi][ni][3]);
        }
    }
}

// ---------------------------------------------------------------------------
// complex helpers
// ---------------------------------------------------------------------------
__device__ __forceinline__ float2 cmul(float2 a, float2 b)
{
    return make_float2(a.x * b.x - a.y * b.y, a.x * b.y + a.y * b.x);
}
__device__ __forceinline__ float2 cmulc(float2 a, float2 b)   // a * conj(b)
{
    return make_float2(a.x * b.x + a.y * b.y, a.y * b.x - a.x * b.y);
}

// ---------------------------------------------------------------------------
// Householder reflection: z -= (2/|v|^2) * <z, conj(v)> * v   (smem, block)
// ---------------------------------------------------------------------------
__device__ __forceinline__ void block_reflect(
    float2* z, const float* __restrict__ vre, const float* __restrict__ vim,
    float (*red)[16], int tid)
{
    float sr = 0.f, si = 0.f, sq = 0.f;
    for (int i = tid; i < FN; i += FT) {
        float zr = z[i].x, zi = z[i].y;
        float vr = vre[i], vi = vim[i];
        sr += zr * vr + zi * vi;
        si += zi * vr - zr * vi;
        sq += vr * vr + vi * vi;
    }
    #pragma unroll
    for (int o = 16; o; o >>= 1) {
        sr += __shfl_xor_sync(0xffffffffu, sr, o);
        si += __shfl_xor_sync(0xffffffffu, si, o);
        sq += __shfl_xor_sync(0xffffffffu, sq, o);
    }
    int w = tid >> 5;
    if ((tid & 31) == 0) { red[0][w] = sr; red[1][w] = si; red[2][w] = sq; }
    __syncthreads();
    sr = si = sq = 0.f;
    #pragma unroll
    for (int i = 0; i < 16; ++i) { sr += red[0][i]; si += red[1][i]; sq += red[2][i]; }
    float f  = 2.0f / sq;
    float fr = f * sr, fi = f * si;
    for (int i = tid; i < FN; i += FT) {
        float vr = vre[i], vi = vim[i];
        float zr = z[i].x, zi = z[i].y;
        z[i] = make_float2(zr - (fr * vr - fi * vi),
                           zi - (fr * vi + fi * vr));
    }
    __syncthreads();
}

// ---------------------------------------------------------------------------
// Fused URNN pipeline. 1 CTA = 1 row. Mixed-radix Stockham: 5x radix-4 + radix-2
// ---------------------------------------------------------------------------
__global__ __launch_bounds__(FT) void urnn_fused_kernel(
    const float* __restrict__ state, const float* __restrict__ gin,
    const float* __restrict__ b_h,
    const float* __restrict__ d1w, const float* __restrict__ r1re, const float* __restrict__ r1im,
    const float* __restrict__ d2w, const float* __restrict__ r2re, const float* __restrict__ r2im,
    const float* __restrict__ d3w, const int* __restrict__ perm,
    float* __restrict__ out)
{
    __shared__ float2 bA[FN];
    __shared__ float2 bB[FN];
    __shared__ float2 tw[512];            // tw[k] = exp(-2*pi*i*k/FN), k<512
    __shared__ float  red[3][16];

    const int tid = threadIdx.x;
    const size_t b = blockIdx.x;
    const float* srow = state + b * (2 * FN);
    const float* grow = gin   + b * (2 * FN);
    float*       orow = out   + b * (2 * FN);

    for (int i = tid; i < 512; i += FT) {
        float s, c;
        __sincosf(-6.283185307179586f * (float)i / (float)FN, &s, &c);
        tw[i] = make_float2(c, s);
    }

    for (int i = tid; i < FN; i += FT) {
        float re = srow[i], im = srow[FN + i];
        float s, c; __sincosf(d1w[i], &s, &c);
        bA[i] = make_float2(c * re - s * im, s * re + c * im);
    }
    __syncthreads();

    float2 *x = bA, *y = bB;

    // ---- forward FFT: 5 radix-4 stages (m=1,4,16,64,256) + radix-2 (m=1024)
    #pragma unroll
    for (int s = 0; s < 5; ++s) {
        const int m = 1 << (2 * s);
        for (int t = tid; t < 512; t += FT) {
            int pm = t & ~(m - 1);
            float2 a0 = x[t], a1 = x[t + 512], a2 = x[t + 1024], a3 = x[t + 1536];
            float2 w1 = tw[pm];
            float2 w2 = cmul(w1, w1);
            float2 w3 = cmul(w2, w1);
            float2 t0 = make_float2(a0.x + a2.x, a0.y + a2.y);
            float2 t1 = make_float2(a0.x - a2.x, a0.y - a2.y);
            float2 t2 = make_float2(a1.x + a3.x, a1.y + a3.y);
            float2 t3 = make_float2(a1.x - a3.x, a1.y - a3.y);
            float2 b0 = make_float2(t0.x + t2.x, t0.y + t2.y);
            float2 b2 = make_float2(t0.x - t2.x, t0.y - t2.y);
            float2 b1 = make_float2(t1.x + t3.y, t1.y - t3.x);   // t1 - i t3
            float2 b3 = make_float2(t1.x - t3.y, t1.y + t3.x);   // t1 + i t3
            int base = t + 3 * pm;
            y[base]         = b0;
            y[base + m]     = cmul(w1, b1);
            y[base + 2 * m] = cmul(w2, b2);
            y[base + 3 * m] = cmul(w3, b3);
        }
        __syncthreads();
        float2* tmp = x; x = y; y = tmp;
    }
    for (int t = tid; t < 1024; t += FT) {
        float2 c0 = x[t], c1 = x[t + 1024];
        y[t]        = make_float2(c0.x + c1.x, c0.y + c1.y);
        y[t + 1024] = make_float2(c0.x - c1.x, c0.y - c1.y);
    }
    __syncthreads();
    { float2* tmp = x; x = y; y = tmp; }

    block_reflect(x, r1re, r1im, red, tid);

    // permutation + diag2
    for (int i = tid; i < FN; i += FT) {
        float2 zp = x[perm[i]];
        float s, c; __sincosf(d2w[i], &s, &c);
        y[i] = make_float2(c * zp.x - s * zp.y, s * zp.x + c * zp.y);
    }
    __syncthreads();
    { float2* tmp = x; x = y; y = tmp; }

    // ---- inverse FFT (conjugate twiddles)
    #pragma unroll
    for (int s = 0; s < 5; ++s) {
        const int m = 1 << (2 * s);
        for (int t = tid; t < 512; t += FT) {
            int pm = t & ~(m - 1);
            float2 a0 = x[t], a1 = x[t + 512], a2 = x[t + 1024], a3 = x[t + 1536];
            float2 w1 = tw[pm];
            float2 w2 = cmul(w1, w1);
            float2 w3 = cmul(w2, w1);
            float2 t0 = make_float2(a0.x + a2.x, a0.y + a2.y);
            float2 t1 = make_float2(a0.x - a2.x, a0.y - a2.y);
            float2 t2 = make_float2(a1.x + a3.x, a1.y + a3.y);
            float2 t3 = make_float2(a1.x - a3.x, a1.y - a3.y);
            float2 b0 = make_float2(t0.x + t2.x, t0.y + t2.y);
            float2 b2 = make_float2(t0.x - t2.x, t0.y - t2.y);
            float2 b1 = make_float2(t1.x - t3.y, t1.y + t3.x);   // t1 + i t3
            float2 b3 = make_float2(t1.x + t3.y, t1.y - t3.x);   // t1 - i t3
            int base = t + 3 * pm;
            y[base]         = b0;
            y[base + m]     = cmulc(b1, w1);
            y[base + 2 * m] = cmulc(b2, w2);
            y[base + 3 * m] = cmulc(b3, w3);
        }
        __syncthreads();
        float2* tmp = x; x = y; y = tmp;
    }
    for (int t = tid; t < 1024; t += FT) {
        float2 c0 = x[t], c1 = x[t + 1024];
        y[t]        = make_float2(c0.x + c1.x, c0.y + c1.y);
        y[t + 1024] = make_float2(c0.x - c1.x, c0.y - c1.y);
    }
    __syncthreads();
    { float2* tmp = x; x = y; y = tmp; }

    block_reflect(x, r2re, r2im, red, tid);

    // diag3 * (1/N) + add inputs_c + modReLU + store
    const float invN = 1.0f / (float)FN;
    for (int i = tid; i < FN; i += FT) {
        float2 zc = x[i];
        float s, c; __sincosf(d3w[i], &s, &c);
        float zr = (c * zc.x - s * zc.y) * invN;
        float zi = (s * zc.x + c * zc.y) * invN;
        float pr = grow[i]      + zr;
        float pi = grow[FN + i] + zi;
        float norm = sqrtf(pr * pr + pi * pi);
        float sc = fmaxf(norm + b_h[i], 0.0f) / (norm + 1e-6f);
        orow[i]      = pr * sc;
        orow[FN + i] = pi * sc;
    }
}

// ---------------------------------------------------------------------------
// Launch
// ---------------------------------------------------------------------------
extern "C" void kernel_launch(void* const* d_in, const int* in_sizes, int n_in,
                              void* d_out, int out_size)
{
    const float* inputs = (const float*)d_in[0];
    const float* state  = (const float*)d_in[1];
    const float* w_ih   = (const float*)d_in[2];
    const float* b_h    = (const float*)d_in[3];
    const float* d1w    = (const float*)d_in[4];
    const float* r1re   = (const float*)d_in[5];
    const float* r1im   = (const float*)d_in[6];
    const float* d2w    = (const float*)d_in[7];
    const float* r2re   = (const float*)d_in[8];
    const float* r2im   = (const float*)d_in[9];
    const float* d3w    = (const float*)d_in[10];
    const int*   perm   = (const int*)d_in[11];
    float* out = (float*)d_out;

    float *gmul; __nv_bfloat16 *Ah, *Al, *Bh, *Bl;
    cudaGetSymbolAddress((void**)&gmul, g_mul);
    cudaGetSymbolAddress((void**)&Ah, g_Ah);
    cudaGetSymbolAddress((void**)&Al, g_Al);
    cudaGetSymbolAddress((void**)&Bh, g_Bh);
    cudaGetSymbolAddress((void**)&Bl, g_Bl);

    // split fp32 -> bf16 hi/lo
    split_kernel<<<(GM * GK) / 256, 256>>>(inputs, Ah, Al, GM * GK);
    split_kernel<<<(GN * GK) / 256, 256>>>(w_ih,   Bh, Bl, GN * GK);

    // tensor-core GEMM (3 bf16 passes -> fp32 accuracy)
    dim3 ggrid(GN / 128, GM / 128);
    gemm_bf16_split<<<ggrid, 256>>>(Ah, Al, Bh, Bl, gmul);

    // fused URNN pipeline
    urnn_fused_kernel<<<GM, FT>>>(state, gmul, b_h,
                                  d1w, r1re, r1im,
                                  d2w, r2re, r2im,
                                  d3w, perm, out);
}

// round 6
// speedup vs baseline: 3.2599x; 1.8398x over previous
#include <cuda_runtime.h>
#include <cuda_fp16.h>
#include <cstdint>

// ---------------------------------------------------------------------------
// Problem constants (B=8192, N_IN=1024, N=2048)
// ---------------------------------------------------------------------------
#define FN   2048
#define FT   512
#define GM   8192
#define GN   4096
#define GK   1024

// Static scratch (no allocs allowed)
__device__ float  g_mul[8192ULL * 4096ULL];   // GEMM output (B, 2N)
__device__ __half g_Af[8192ULL * 1024ULL];
__device__ __half g_Bf[4096ULL * 1024ULL];

// ---------------------------------------------------------------------------
// fp32 -> fp16 convert
// ---------------------------------------------------------------------------
__global__ void cvt_kernel(const float* __restrict__ src,
                           __half* __restrict__ dst, int n)
{
    int i = blockIdx.x * blockDim.x + threadIdx.x;
    if (i < n) dst[i] = __float2half(src[i]);
}

// ---------------------------------------------------------------------------
// fp16 GEMM:  C[m,n] = sum_k A[m,k]*B[n,k]   (fp32 accumulate)
// 128x128x32 tiles, 256 thr (8 warps 4x2), mma.sync m16n8k16, cp.async 2-stage
// ---------------------------------------------------------------------------
__device__ __forceinline__ void cp_async16(void* smem, const void* gmem)
{
    uint32_t s = (uint32_t)__cvta_generic_to_shared(smem);
    asm volatile("cp.async.cg.shared.global [%0], [%1], 16;\n" :: "r"(s), "l"(gmem));
}

__device__ __forceinline__ void ldsm_x4(uint32_t* r, const void* p)
{
    uint32_t s = (uint32_t)__cvta_generic_to_shared(p);
    asm volatile("ldmatrix.sync.aligned.m8n8.x4.shared.b16 {%0,%1,%2,%3}, [%4];\n"
                 : "=r"(r[0]), "=r"(r[1]), "=r"(r[2]), "=r"(r[3]) : "r"(s));
}

__device__ __forceinline__ void mma16816(float* c, const uint32_t* a, const uint32_t* b)
{
    asm volatile(
        "mma.sync.aligned.m16n8k16.row.col.f32.f16.f16.f32 "
        "{%0,%1,%2,%3}, {%4,%5,%6,%7}, {%8,%9}, {%0,%1,%2,%3};\n"
        : "+f"(c[0]), "+f"(c[1]), "+f"(c[2]), "+f"(c[3])
        : "r"(a[0]), "r"(a[1]), "r"(a[2]), "r"(a[3]), "r"(b[0]), "r"(b[1]));
}

#define SROW 40   // smem row stride in halves (80B: conflict-free for ldmatrix)

__global__ __launch_bounds__(256) void gemm_fp16(
    const __half* __restrict__ Af, const __half* __restrict__ Bf,
    float* __restrict__ C)
{
    __shared__ __half As[2][128 * SROW];
    __shared__ __half Bs[2][128 * SROW];

    const int tid  = threadIdx.x;
    const int wid  = tid >> 5, lane = tid & 31;
    const int wm   = wid >> 1, wn = wid & 1;     // warp grid 4(M) x 2(N)
    const int bm   = blockIdx.y * 128, bn = blockIdx.x * 128;

    const int NIT = GK / 32;                     // 32 tile iterations

    float acc[2][8][4];
    #pragma unroll
    for (int mi = 0; mi < 2; ++mi)
        #pragma unroll
        for (int ni = 0; ni < 8; ++ni)
            #pragma unroll
            for (int j = 0; j < 4; ++j) acc[mi][ni][j] = 0.0f;

    auto load_tiles = [&](int st, int it) {
        int kk = it * 32;
        #pragma unroll
        for (int j = 0; j < 2; ++j) {
            int c   = tid + j * 256;             // 512 16B-chunks per operand
            int row = c >> 2;
            int off = (c & 3) * 8;               // halves
            cp_async16(&As[st][row * SROW + off],
                       Af + (size_t)(bm + row) * GK + kk + off);
            cp_async16(&Bs[st][row * SROW + off],
                       Bf + (size_t)(bn + row) * GK + kk + off);
        }
        asm volatile("cp.async.commit_group;\n");
    };

    load_tiles(0, 0);

    for (int it = 0; it < NIT; ++it) {
        int st = it & 1;
        if (it + 1 < NIT) {
            load_tiles(st ^ 1, it + 1);
            asm volatile("cp.async.wait_group 1;\n");
        } else {
            asm volatile("cp.async.wait_group 0;\n");
        }
        __syncthreads();

        #pragma unroll
        for (int ks = 0; ks < 2; ++ks) {
            uint32_t a[2][4], b[8][2];
            int ra = wm * 32 + (lane & 7) + ((lane & 8) ? 8 : 0);
            int ca = ks * 16 + ((lane & 16) ? 8 : 0);
            #pragma unroll
            for (int mi = 0; mi < 2; ++mi)
                ldsm_x4(a[mi], &As[st][(ra + mi * 16) * SROW + ca]);
            int rb = wn * 64 + (lane & 7) + ((lane & 16) ? 8 : 0);
            int cb = ks * 16 + ((lane & 8) ? 8 : 0);
            #pragma unroll
            for (int g = 0; g < 4; ++g) {
                uint32_t r[4];
                ldsm_x4(r, &Bs[st][(rb + g * 16) * SROW + cb]);
                b[2 * g][0] = r[0]; b[2 * g][1] = r[1];
                b[2 * g + 1][0] = r[2]; b[2 * g + 1][1] = r[3];
            }
            #pragma unroll
            for (int mi = 0; mi < 2; ++mi)
                #pragma unroll
                for (int ni = 0; ni < 8; ++ni)
                    mma16816(acc[mi][ni], a[mi], b[ni]);
        }
        __syncthreads();
    }

    #pragma unroll
    for (int mi = 0; mi < 2; ++mi) {
        #pragma unroll
        for (int ni = 0; ni < 8; ++ni) {
            int row = bm + wm * 32 + mi * 16 + (lane >> 2);
            int col = bn + wn * 64 + ni * 8 + (lane & 3) * 2;
            float2* p0 = (float2*)(C + (size_t)row * GN + col);
            float2* p1 = (float2*)(C + (size_t)(row + 8) * GN + col);
            *p0 = make_float2(acc[mi][ni][0], acc[mi][ni][1]);
            *p1 = make_float2(acc[mi][ni][2], acc[mi][ni][3]);
        }
    }
}

// ---------------------------------------------------------------------------
// complex helpers
// ---------------------------------------------------------------------------
__device__ __forceinline__ float2 cmul(float2 a, float2 b)
{
    return make_float2(a.x * b.x - a.y * b.y, a.x * b.y + a.y * b.x);
}
__device__ __forceinline__ float2 cmulc(float2 a, float2 b)   // a * conj(b)
{
    return make_float2(a.x * b.x + a.y * b.y, a.y * b.x - a.x * b.y);
}

// ---------------------------------------------------------------------------
// Householder reflection: z -= (2/|v|^2) * <z, conj(v)> * v
// ---------------------------------------------------------------------------
__device__ __forceinline__ void block_reflect(
    float2* z, const float* __restrict__ vre, const float* __restrict__ vim,
    float (*red)[16], int tid)
{
    float sr = 0.f, si = 0.f, sq = 0.f;
    for (int i = tid; i < FN; i += FT) {
        float zr = z[i].x, zi = z[i].y;
        float vr = vre[i], vi = vim[i];
        sr += zr * vr + zi * vi;
        si += zi * vr - zr * vi;
        sq += vr * vr + vi * vi;
    }
    #pragma unroll
    for (int o = 16; o; o >>= 1) {
        sr += __shfl_xor_sync(0xffffffffu, sr, o);
        si += __shfl_xor_sync(0xffffffffu, si, o);
        sq += __shfl_xor_sync(0xffffffffu, sq, o);
    }
    int w = tid >> 5;
    if ((tid & 31) == 0) { red[0][w] = sr; red[1][w] = si; red[2][w] = sq; }
    __syncthreads();
    sr = si = sq = 0.f;
    #pragma unroll
    for (int i = 0; i < 16; ++i) { sr += red[0][i]; si += red[1][i]; sq += red[2][i]; }
    float f  = 2.0f / sq;
    float fr = f * sr, fi = f * si;
    for (int i = tid; i < FN; i += FT) {
        float vr = vre[i], vi = vim[i];
        float zr = z[i].x, zi = z[i].y;
        z[i] = make_float2(zr - (fr * vr - fi * vi),
                           zi - (fr * vi + fi * vr));
    }
    __syncthreads();
}

// ---------------------------------------------------------------------------
// Fused URNN pipeline. 1 CTA = 1 row. 5x radix-4 + radix-2 Stockham.
// ---------------------------------------------------------------------------
__global__ __launch_bounds__(FT, 3) void urnn_fused_kernel(
    const float* __restrict__ state, const float* __restrict__ gin,
    const float* __restrict__ b_h,
    const float* __restrict__ d1w, const float* __restrict__ r1re, const float* __restrict__ r1im,
    const float* __restrict__ d2w, const float* __restrict__ r2re, const float* __restrict__ r2im,
    const float* __restrict__ d3w, const int* __restrict__ perm,
    float* __restrict__ out)
{
    __shared__ float2 bA[FN];
    __shared__ float2 bB[FN];
    __shared__ float2 tw[512];
    __shared__ float  red[3][16];

    const int tid = threadIdx.x;
    const size_t b = blockIdx.x;
    const float* srow = state + b * (2 * FN);
    const float* grow = gin   + b * (2 * FN);
    float*       orow = out   + b * (2 * FN);

    for (int i = tid; i < 512; i += FT) {
        float s, c;
        __sincosf(-6.283185307179586f * (float)i / (float)FN, &s, &c);
        tw[i] = make_float2(c, s);
    }

    for (int i = tid; i < FN; i += FT) {
        float re = srow[i], im = srow[FN + i];
        float s, c; __sincosf(d1w[i], &s, &c);
        bA[i] = make_float2(c * re - s * im, s * re + c * im);
    }
    __syncthreads();

    float2 *x = bA, *y = bB;

    #pragma unroll
    for (int s = 0; s < 5; ++s) {
        const int m = 1 << (2 * s);
        for (int t = tid; t < 512; t += FT) {
            int pm = t & ~(m - 1);
            float2 a0 = x[t], a1 = x[t + 512], a2 = x[t + 1024], a3 = x[t + 1536];
            float2 w1 = tw[pm];
            float2 w2 = cmul(w1, w1);
            float2 w3 = cmul(w2, w1);
            float2 t0 = make_float2(a0.x + a2.x, a0.y + a2.y);
            float2 t1 = make_float2(a0.x - a2.x, a0.y - a2.y);
            float2 t2 = make_float2(a1.x + a3.x, a1.y + a3.y);
            float2 t3 = make_float2(a1.x - a3.x, a1.y - a3.y);
            float2 b0 = make_float2(t0.x + t2.x, t0.y + t2.y);
            float2 b2 = make_float2(t0.x - t2.x, t0.y - t2.y);
            float2 b1 = make_float2(t1.x + t3.y, t1.y - t3.x);
            float2 b3 = make_float2(t1.x - t3.y, t1.y + t3.x);
            int base = t + 3 * pm;
            y[base]         = b0;
            y[base + m]     = cmul(w1, b1);
            y[base + 2 * m] = cmul(w2, b2);
            y[base + 3 * m] = cmul(w3, b3);
        }
        __syncthreads();
        float2* tmp = x; x = y; y = tmp;
    }
    for (int t = tid; t < 1024; t += FT) {
        float2 c0 = x[t], c1 = x[t + 1024];
        y[t]        = make_float2(c0.x + c1.x, c0.y + c1.y);
        y[t + 1024] = make_float2(c0.x - c1.x, c0.y - c1.y);
    }
    __syncthreads();
    { float2* tmp = x; x = y; y = tmp; }

    block_reflect(x, r1re, r1im, red, tid);

    for (int i = tid; i < FN; i += FT) {
        float2 zp = x[perm[i]];
        float s, c; __sincosf(d2w[i], &s, &c);
        y[i] = make_float2(c * zp.x - s * zp.y, s * zp.x + c * zp.y);
    }
    __syncthreads();
    { float2* tmp = x; x = y; y = tmp; }

    #pragma unroll
    for (int s = 0; s < 5; ++s) {
        const int m = 1 << (2 * s);
        for (int t = tid; t < 512; t += FT) {
            int pm = t & ~(m - 1);
            float2 a0 = x[t], a1 = x[t + 512], a2 = x[t + 1024], a3 = x[t + 1536];
            float2 w1 = tw[pm];
            float2 w2 = cmul(w1, w1);
            float2 w3 = cmul(w2, w1);
            float2 t0 = make_float2(a0.x + a2.x, a0.y + a2.y);
            float2 t1 = make_float2(a0.x - a2.x, a0.y - a2.y);
            float2 t2 = make_float2(a1.x + a3.x, a1.y + a3.y);
            float2 t3 = make_float2(a1.x - a3.x, a1.y - a3.y);
            float2 b0 = make_float2(t0.x + t2.x, t0.y + t2.y);
            float2 b2 = make_float2(t0.x - t2.x, t0.y - t2.y);
            float2 b1 = make_float2(t1.x - t3.y, t1.y + t3.x);
            float2 b3 = make_float2(t1.x + t3.y, t1.y - t3.x);
            int base = t + 3 * pm;
            y[base]         = b0;
            y[base + m]     = cmulc(b1, w1);
            y[base + 2 * m] = cmulc(b2, w2);
            y[base + 3 * m] = cmulc(b3, w3);
        }
        __syncthreads();
        float2* tmp = x; x = y; y = tmp;
    }
    for (int t = tid; t < 1024; t += FT) {
        float2 c0 = x[t], c1 = x[t + 1024];
        y[t]        = make_float2(c0.x + c1.x, c0.y + c1.y);
        y[t + 1024] = make_float2(c0.x - c1.x, c0.y - c1.y);
    }
    __syncthreads();
    { float2* tmp = x; x = y; y = tmp; }

    block_reflect(x, r2re, r2im, red, tid);

    const float invN = 1.0f / (float)FN;
    for (int i = tid; i < FN; i += FT) {
        float2 zc = x[i];
        float s, c; __sincosf(d3w[i], &s, &c);
        float zr = (c * zc.x - s * zc.y) * invN;
        float zi = (s * zc.x + c * zc.y) * invN;
        float pr = grow[i]      + zr;
        float pi = grow[FN + i] + zi;
        float norm = sqrtf(pr * pr + pi * pi);
        float sc = fmaxf(norm + b_h[i], 0.0f) / (norm + 1e-6f);
        orow[i]      = pr * sc;
        orow[FN + i] = pi * sc;
    }
}

// ---------------------------------------------------------------------------
// Launch
// ---------------------------------------------------------------------------
extern "C" void kernel_launch(void* const* d_in, const int* in_sizes, int n_in,
                              void* d_out, int out_size)
{
    const float* inputs = (const float*)d_in[0];
    const float* state  = (const float*)d_in[1];
    const float* w_ih   = (const float*)d_in[2];
    const float* b_h    = (const float*)d_in[3];
    const float* d1w    = (const float*)d_in[4];
    const float* r1re   = (const float*)d_in[5];
    const float* r1im   = (const float*)d_in[6];
    const float* d2w    = (const float*)d_in[7];
    const float* r2re   = (const float*)d_in[8];
    const float* r2im   = (const float*)d_in[9];
    const float* d3w    = (const float*)d_in[10];
    const int*   perm   = (const int*)d_in[11];
    float* out = (float*)d_out;

    float *gmul; __half *Af, *Bf;
    cudaGetSymbolAddress((void**)&gmul, g_mul);
    cudaGetSymbolAddress((void**)&Af, g_Af);
    cudaGetSymbolAddress((void**)&Bf, g_Bf);

    cvt_kernel<<<(GM * GK) / 256, 256>>>(inputs, Af, GM * GK);
    cvt_kernel<<<(GN * GK) / 256, 256>>>(w_ih,   Bf, GN * GK);

    dim3 ggrid(GN / 128, GM / 128);
    gemm_fp16<<<ggrid, 256>>>(Af, Bf, gmul);

    urnn_fused_kernel<<<GM, FT>>>(state, gmul, b_h,
                                  d1w, r1re, r1im,
                                  d2w, r2re, r2im,
                                  d3w, perm, out);
}

// round 7
// speedup vs baseline: 3.6896x; 1.1318x over previous
#include <cuda_runtime.h>
#include <cuda_fp16.h>
#include <cstdint>

// ---------------------------------------------------------------------------
// Problem constants (B=8192, N_IN=1024, N=2048)
// ---------------------------------------------------------------------------
#define FN   2048
#define FT   512
#define GM   8192
#define GN   4096
#define GK   1024

// Bank-conflict-free smem swizzle (bijection; XOR bits[4:6) into [0:4))
#define SW(i) ((i) ^ ((((i) >> 4) & 3) * 5))

// Static scratch (no allocs allowed)
__device__ float  g_mul[8192ULL * 4096ULL];   // GEMM output (B, 2N)
__device__ __half g_Af[8192ULL * 1024ULL];
__device__ __half g_Bf[4096ULL * 1024ULL];

// ---------------------------------------------------------------------------
// fp32 -> fp16 convert
// ---------------------------------------------------------------------------
__global__ void cvt_kernel(const float* __restrict__ src,
                           __half* __restrict__ dst, int n)
{
    int i = blockIdx.x * blockDim.x + threadIdx.x;
    if (i < n) dst[i] = __float2half(src[i]);
}

// ---------------------------------------------------------------------------
// fp16 GEMM:  C[m,n] = sum_k A[m,k]*B[n,k]   (fp32 accumulate)  [unchanged]
// ---------------------------------------------------------------------------
__device__ __forceinline__ void cp_async16(void* smem, const void* gmem)
{
    uint32_t s = (uint32_t)__cvta_generic_to_shared(smem);
    asm volatile("cp.async.cg.shared.global [%0], [%1], 16;\n" :: "r"(s), "l"(gmem));
}

__device__ __forceinline__ void ldsm_x4(uint32_t* r, const void* p)
{
    uint32_t s = (uint32_t)__cvta_generic_to_shared(p);
    asm volatile("ldmatrix.sync.aligned.m8n8.x4.shared.b16 {%0,%1,%2,%3}, [%4];\n"
                 : "=r"(r[0]), "=r"(r[1]), "=r"(r[2]), "=r"(r[3]) : "r"(s));
}

__device__ __forceinline__ void mma16816(float* c, const uint32_t* a, const uint32_t* b)
{
    asm volatile(
        "mma.sync.aligned.m16n8k16.row.col.f32.f16.f16.f32 "
        "{%0,%1,%2,%3}, {%4,%5,%6,%7}, {%8,%9}, {%0,%1,%2,%3};\n"
        : "+f"(c[0]), "+f"(c[1]), "+f"(c[2]), "+f"(c[3])
        : "r"(a[0]), "r"(a[1]), "r"(a[2]), "r"(a[3]), "r"(b[0]), "r"(b[1]));
}

#define SROW 40

__global__ __launch_bounds__(256) void gemm_fp16(
    const __half* __restrict__ Af, const __half* __restrict__ Bf,
    float* __restrict__ C)
{
    __shared__ __half As[2][128 * SROW];
    __shared__ __half Bs[2][128 * SROW];

    const int tid  = threadIdx.x;
    const int wid  = tid >> 5, lane = tid & 31;
    const int wm   = wid >> 1, wn = wid & 1;
    const int bm   = blockIdx.y * 128, bn = blockIdx.x * 128;

    const int NIT = GK / 32;

    float acc[2][8][4];
    #pragma unroll
    for (int mi = 0; mi < 2; ++mi)
        #pragma unroll
        for (int ni = 0; ni < 8; ++ni)
            #pragma unroll
            for (int j = 0; j < 4; ++j) acc[mi][ni][j] = 0.0f;

    auto load_tiles = [&](int st, int it) {
        int kk = it * 32;
        #pragma unroll
        for (int j = 0; j < 2; ++j) {
            int c   = tid + j * 256;
            int row = c >> 2;
            int off = (c & 3) * 8;
            cp_async16(&As[st][row * SROW + off],
                       Af + (size_t)(bm + row) * GK + kk + off);
            cp_async16(&Bs[st][row * SROW + off],
                       Bf + (size_t)(bn + row) * GK + kk + off);
        }
        asm volatile("cp.async.commit_group;\n");
    };

    load_tiles(0, 0);

    for (int it = 0; it < NIT; ++it) {
        int st = it & 1;
        if (it + 1 < NIT) {
            load_tiles(st ^ 1, it + 1);
            asm volatile("cp.async.wait_group 1;\n");
        } else {
            asm volatile("cp.async.wait_group 0;\n");
        }
        __syncthreads();

        #pragma unroll
        for (int ks = 0; ks < 2; ++ks) {
            uint32_t a[2][4], b[8][2];
            int ra = wm * 32 + (lane & 7) + ((lane & 8) ? 8 : 0);
            int ca = ks * 16 + ((lane & 16) ? 8 : 0);
            #pragma unroll
            for (int mi = 0; mi < 2; ++mi)
                ldsm_x4(a[mi], &As[st][(ra + mi * 16) * SROW + ca]);
            int rb = wn * 64 + (lane & 7) + ((lane & 16) ? 8 : 0);
            int cb = ks * 16 + ((lane & 8) ? 8 : 0);
            #pragma unroll
            for (int g = 0; g < 4; ++g) {
                uint32_t r[4];
                ldsm_x4(r, &Bs[st][(rb + g * 16) * SROW + cb]);
                b[2 * g][0] = r[0]; b[2 * g][1] = r[1];
                b[2 * g + 1][0] = r[2]; b[2 * g + 1][1] = r[3];
            }
            #pragma unroll
            for (int mi = 0; mi < 2; ++mi)
                #pragma unroll
                for (int ni = 0; ni < 8; ++ni)
                    mma16816(acc[mi][ni], a[mi], b[ni]);
        }
        __syncthreads();
    }

    #pragma unroll
    for (int mi = 0; mi < 2; ++mi) {
        #pragma unroll
        for (int ni = 0; ni < 8; ++ni) {
            int row = bm + wm * 32 + mi * 16 + (lane >> 2);
            int col = bn + wn * 64 + ni * 8 + (lane & 3) * 2;
            float2* p0 = (float2*)(C + (size_t)row * GN + col);
            float2* p1 = (float2*)(C + (size_t)(row + 8) * GN + col);
            *p0 = make_float2(acc[mi][ni][0], acc[mi][ni][1]);
            *p1 = make_float2(acc[mi][ni][2], acc[mi][ni][3]);
        }
    }
}

// ---------------------------------------------------------------------------
// complex helpers
// ---------------------------------------------------------------------------
__device__ __forceinline__ float2 cmul(float2 a, float2 b)
{
    return make_float2(a.x * b.x - a.y * b.y, a.x * b.y + a.y * b.x);
}
__device__ __forceinline__ float2 cmulc(float2 a, float2 b)   // a * conj(b)
{
    return make_float2(a.x * b.x + a.y * b.y, a.y * b.x - a.x * b.y);
}

// ---------------------------------------------------------------------------
// Reflection dot: returns (fr, fi) with f = 2 <z, conj(v)> / |v|^2.
// Reads z (swizzled smem), does NOT modify it.
// ---------------------------------------------------------------------------
__device__ __forceinline__ float2 reflect_factor(
    const float2* z, const float* __restrict__ vre, const float* __restrict__ vim,
    float (*red)[16], int tid)
{
    float sr = 0.f, si = 0.f, sq = 0.f;
    for (int i = tid; i < FN; i += FT) {
        float2 zz = z[SW(i)];
        float vr = vre[i], vi = vim[i];
        sr += zz.x * vr + zz.y * vi;
        si += zz.y * vr - zz.x * vi;
        sq += vr * vr + vi * vi;
    }
    #pragma unroll
    for (int o = 16; o; o >>= 1) {
        sr += __shfl_xor_sync(0xffffffffu, sr, o);
        si += __shfl_xor_sync(0xffffffffu, si, o);
        sq += __shfl_xor_sync(0xffffffffu, sq, o);
    }
    int w = tid >> 5;
    if ((tid & 31) == 0) { red[0][w] = sr; red[1][w] = si; red[2][w] = sq; }
    __syncthreads();
    sr = si = sq = 0.f;
    #pragma unroll
    for (int i = 0; i < 16; ++i) { sr += red[0][i]; si += red[1][i]; sq += red[2][i]; }
    __syncthreads();                       // red reusable afterwards
    float f = 2.0f / sq;
    return make_float2(f * sr, f * si);
}

// ---------------------------------------------------------------------------
// Fused URNN pipeline. 1 CTA = 1 row. Swizzled smem, fused edge passes.
// ---------------------------------------------------------------------------
__global__ __launch_bounds__(FT, 3) void urnn_fused_kernel(
    const float* __restrict__ state, const float* __restrict__ gin,
    const float* __restrict__ b_h,
    const float* __restrict__ d1w, const float* __restrict__ r1re, const float* __restrict__ r1im,
    const float* __restrict__ d2w, const float* __restrict__ r2re, const float* __restrict__ r2im,
    const float* __restrict__ d3w, const int* __restrict__ perm,
    float* __restrict__ out)
{
    __shared__ float2 bA[FN];
    __shared__ float2 bB[FN];
    __shared__ float2 tw[512];
    __shared__ float  red[3][16];

    const int tid = threadIdx.x;
    const size_t b = blockIdx.x;
    const float* srow = state + b * (2 * FN);
    const float* grow = gin   + b * (2 * FN);
    float*       orow = out   + b * (2 * FN);

    for (int i = tid; i < 512; i += FT) {
        float s, c;
        __sincosf(-6.283185307179586f * (float)i / (float)FN, &s, &c);
        tw[i] = make_float2(c, s);
    }
    __syncthreads();

    float2 *x = bA, *y = bB;

    // ---- FWD stage 0 (m=1) fused with global load + diag1 ----
    for (int t = tid; t < 512; t += FT) {
        float2 a0, a1, a2, a3;
        {
            float re, im, s, c;
            re = srow[t];        im = srow[FN + t];        __sincosf(d1w[t], &s, &c);
            a0 = make_float2(c * re - s * im, s * re + c * im);
            re = srow[t + 512];  im = srow[FN + t + 512];  __sincosf(d1w[t + 512], &s, &c);
            a1 = make_float2(c * re - s * im, s * re + c * im);
            re = srow[t + 1024]; im = srow[FN + t + 1024]; __sincosf(d1w[t + 1024], &s, &c);
            a2 = make_float2(c * re - s * im, s * re + c * im);
            re = srow[t + 1536]; im = srow[FN + t + 1536]; __sincosf(d1w[t + 1536], &s, &c);
            a3 = make_float2(c * re - s * im, s * re + c * im);
        }
        float2 w1 = tw[t];
        float2 w2 = cmul(w1, w1);
        float2 w3 = cmul(w2, w1);
        float2 t0 = make_float2(a0.x + a2.x, a0.y + a2.y);
        float2 t1 = make_float2(a0.x - a2.x, a0.y - a2.y);
        float2 t2 = make_float2(a1.x + a3.x, a1.y + a3.y);
        float2 t3 = make_float2(a1.x - a3.x, a1.y - a3.y);
        float2 b0 = make_float2(t0.x + t2.x, t0.y + t2.y);
        float2 b2 = make_float2(t0.x - t2.x, t0.y - t2.y);
        float2 b1 = make_float2(t1.x + t3.y, t1.y - t3.x);
        float2 b3 = make_float2(t1.x - t3.y, t1.y + t3.x);
        int base = 4 * t;
        y[SW(base)]     = b0;
        y[SW(base + 1)] = cmul(w1, b1);
        y[SW(base + 2)] = cmul(w2, b2);
        y[SW(base + 3)] = cmul(w3, b3);
    }
    __syncthreads();
    { float2* tmp = x; x = y; y = tmp; }

    // ---- FWD stages m=4..256 ----
    #pragma unroll
    for (int s = 1; s < 5; ++s) {
        const int m = 1 << (2 * s);
        for (int t = tid; t < 512; t += FT) {
            int pm = t & ~(m - 1);
            float2 a0 = x[SW(t)], a1 = x[SW(t + 512)],
                   a2 = x[SW(t + 1024)], a3 = x[SW(t + 1536)];
            float2 w1 = tw[pm];
            float2 w2 = cmul(w1, w1);
            float2 w3 = cmul(w2, w1);
            float2 t0 = make_float2(a0.x + a2.x, a0.y + a2.y);
            float2 t1 = make_float2(a0.x - a2.x, a0.y - a2.y);
            float2 t2 = make_float2(a1.x + a3.x, a1.y + a3.y);
            float2 t3 = make_float2(a1.x - a3.x, a1.y - a3.y);
            float2 b0 = make_float2(t0.x + t2.x, t0.y + t2.y);
            float2 b2 = make_float2(t0.x - t2.x, t0.y - t2.y);
            float2 b1 = make_float2(t1.x + t3.y, t1.y - t3.x);
            float2 b3 = make_float2(t1.x - t3.y, t1.y + t3.x);
            int base = t + 3 * pm;
            y[SW(base)]         = b0;
            y[SW(base + m)]     = cmul(w1, b1);
            y[SW(base + 2 * m)] = cmul(w2, b2);
            y[SW(base + 3 * m)] = cmul(w3, b3);
        }
        __syncthreads();
        float2* tmp = x; x = y; y = tmp;
    }
    // radix-2 tail
    for (int t = tid; t < 1024; t += FT) {
        float2 c0 = x[SW(t)], c1 = x[SW(t + 1024)];
        y[SW(t)]        = make_float2(c0.x + c1.x, c0.y + c1.y);
        y[SW(t + 1024)] = make_float2(c0.x - c1.x, c0.y - c1.y);
    }
    __syncthreads();
    { float2* tmp = x; x = y; y = tmp; }

    // ---- reflect 1: factors only (update fused into next pass) ----
    float2 f1 = reflect_factor(x, r1re, r1im, red, tid);

    // ---- IFFT stage 0 (m=1) fused with reflect1-update + perm + diag2 ----
    for (int t = tid; t < 512; t += FT) {
        float2 a[4];
        #pragma unroll
        for (int q = 0; q < 4; ++q) {
            int i = t + q * 512;
            int p = perm[i];
            float2 zp = x[SW(p)];
            float vr = r1re[p], vi = r1im[p];
            zp.x -= f1.x * vr - f1.y * vi;
            zp.y -= f1.x * vi + f1.y * vr;
            float s, c; __sincosf(d2w[i], &s, &c);
            a[q] = make_float2(c * zp.x - s * zp.y, s * zp.x + c * zp.y);
        }
        float2 w1 = tw[t];
        float2 w2 = cmul(w1, w1);
        float2 w3 = cmul(w2, w1);
        float2 t0 = make_float2(a[0].x + a[2].x, a[0].y + a[2].y);
        float2 t1 = make_float2(a[0].x - a[2].x, a[0].y - a[2].y);
        float2 t2 = make_float2(a[1].x + a[3].x, a[1].y + a[3].y);
        float2 t3 = make_float2(a[1].x - a[3].x, a[1].y - a[3].y);
        float2 b0 = make_float2(t0.x + t2.x, t0.y + t2.y);
        float2 b2 = make_float2(t0.x - t2.x, t0.y - t2.y);
        float2 b1 = make_float2(t1.x - t3.y, t1.y + t3.x);
        float2 b3 = make_float2(t1.x + t3.y, t1.y - t3.x);
        int base = 4 * t;
        y[SW(base)]     = b0;
        y[SW(base + 1)] = cmulc(b1, w1);
        y[SW(base + 2)] = cmulc(b2, w2);
        y[SW(base + 3)] = cmulc(b3, w3);
    }
    __syncthreads();
    { float2* tmp = x; x = y; y = tmp; }

    // ---- IFFT stages m=4..256 ----
    #pragma unroll
    for (int s = 1; s < 5; ++s) {
        const int m = 1 << (2 * s);
        for (int t = tid; t < 512; t += FT) {
            int pm = t & ~(m - 1);
            float2 a0 = x[SW(t)], a1 = x[SW(t + 512)],
                   a2 = x[SW(t + 1024)], a3 = x[SW(t + 1536)];
            float2 w1 = tw[pm];
            float2 w2 = cmul(w1, w1);
            float2 w3 = cmul(w2, w1);
            float2 t0 = make_float2(a0.x + a2.x, a0.y + a2.y);
            float2 t1 = make_float2(a0.x - a2.x, a0.y - a2.y);
            float2 t2 = make_float2(a1.x + a3.x, a1.y + a3.y);
            float2 t3 = make_float2(a1.x - a3.x, a1.y - a3.y);
            float2 b0 = make_float2(t0.x + t2.x, t0.y + t2.y);
            float2 b2 = make_float2(t0.x - t2.x, t0.y - t2.y);
            float2 b1 = make_float2(t1.x - t3.y, t1.y + t3.x);
            float2 b3 = make_float2(t1.x + t3.y, t1.y - t3.x);
            int base = t + 3 * pm;
            y[SW(base)]         = b0;
            y[SW(base + m)]     = cmulc(b1, w1);
            y[SW(base + 2 * m)] = cmulc(b2, w2);
            y[SW(base + 3 * m)] = cmulc(b3, w3);
        }
        __syncthreads();
        float2* tmp = x; x = y; y = tmp;
    }
    for (int t = tid; t < 1024; t += FT) {
        float2 c0 = x[SW(t)], c1 = x[SW(t + 1024)];
        y[SW(t)]        = make_float2(c0.x + c1.x, c0.y + c1.y);
        y[SW(t + 1024)] = make_float2(c0.x - c1.x, c0.y - c1.y);
    }
    __syncthreads();
    { float2* tmp = x; x = y; y = tmp; }

    // ---- reflect 2: factors only ----
    float2 f2 = reflect_factor(x, r2re, r2im, red, tid);

    // ---- final: reflect2-update + diag3*(1/N) + add inputs + modReLU ----
    const float invN = 1.0f / (float)FN;
    for (int i = tid; i < FN; i += FT) {
        float2 zc = x[SW(i)];
        float vr = r2re[i], vi = r2im[i];
        zc.x -= f2.x * vr - f2.y * vi;
        zc.y -= f2.x * vi + f2.y * vr;
        float s, c; __sincosf(d3w[i], &s, &c);
        float zr = (c * zc.x - s * zc.y) * invN;
        float zi = (s * zc.x + c * zc.y) * invN;
        float pr = grow[i]      + zr;
        float pi = grow[FN + i] + zi;
        float norm = sqrtf(pr * pr + pi * pi);
        float sc = fmaxf(norm + b_h[i], 0.0f) / (norm + 1e-6f);
        orow[i]      = pr * sc;
        orow[FN + i] = pi * sc;
    }
}

// ---------------------------------------------------------------------------
// Launch
// ---------------------------------------------------------------------------
extern "C" void kernel_launch(void* const* d_in, const int* in_sizes, int n_in,
                              void* d_out, int out_size)
{
    const float* inputs = (const float*)d_in[0];
    const float* state  = (const float*)d_in[1];
    const float* w_ih   = (const float*)d_in[2];
    const float* b_h    = (const float*)d_in[3];
    const float* d1w    = (const float*)d_in[4];
    const float* r1re   = (const float*)d_in[5];
    const float* r1im   = (const float*)d_in[6];
    const float* d2w    = (const float*)d_in[7];
    const float* r2re   = (const float*)d_in[8];
    const float* r2im   = (const float*)d_in[9];
    const float* d3w    = (const float*)d_in[10];
    const int*   perm   = (const int*)d_in[11];
    float* out = (float*)d_out;

    float *gmul; __half *Af, *Bf;
    cudaGetSymbolAddress((void**)&gmul, g_mul);
    cudaGetSymbolAddress((void**)&Af, g_Af);
    cudaGetSymbolAddress((void**)&Bf, g_Bf);

    cvt_kernel<<<(GM * GK) / 256, 256>>>(inputs, Af, GM * GK);
    cvt_kernel<<<(GN * GK) / 256, 256>>>(w_ih,   Bf, GN * GK);

    dim3 ggrid(GN / 128, GM / 128);
    gemm_fp16<<<ggrid, 256>>>(Af, Bf, gmul);

    urnn_fused_kernel<<<GM, FT>>>(state, gmul, b_h,
                                  d1w, r1re, r1im,
                                  d2w, r2re, r2im,
                                  d3w, perm, out);
}